// round 1
// baseline (speedup 1.0000x reference)
#include <cuda_runtime.h>
#include <cstdint>
#include <cstddef>

#define B_   4
#define C_   512
#define N_   4096
#define CQ_  64
#define SCALE_ 0.125f   // (C/8)^-0.5 = 64^-0.5

// ---------------- device scratch (static globals: no allocations) ----------
__device__ float g_q[B_ * CQ_ * N_];                 // [b][q][n]   4 MB
__device__ float g_k[B_ * CQ_ * N_];                 // [b][q][n]   4 MB
__device__ float g_v[B_ * C_ * N_];                  // [b][c][n]  33.5 MB
__device__ float g_p[(size_t)B_ * N_ * N_];          // [b][i][j]  268 MB (exp(E - max))
__device__ float g_rowsum[B_ * N_];

// load 8 consecutive floats from shared via two float4
#define LD8(dst, ptr)                                              \
    do {                                                           \
        float4 _u0 = *(const float4*)((ptr));                      \
        float4 _u1 = *(const float4*)((ptr) + 4);                  \
        (dst)[0]=_u0.x; (dst)[1]=_u0.y; (dst)[2]=_u0.z; (dst)[3]=_u0.w; \
        (dst)[4]=_u1.x; (dst)[5]=_u1.y; (dst)[6]=_u1.z; (dst)[7]=_u1.w; \
    } while (0)

// ---------------------------------------------------------------------------
// Q/K projection: Y[b][m][n] = sum_k W[m][k] * X[b][k][n] + bias[m]
// M = 64, tile BN=128, BK=32, 256 threads, 4x8 microtile
// which == 0 -> g_q, which == 1 -> g_k
// ---------------------------------------------------------------------------
__global__ __launch_bounds__(256) void qk_proj_kernel(
    const float* __restrict__ W, const float* __restrict__ bias,
    const float* __restrict__ X, int which)
{
    __shared__ float Ws[32][68];    // [k][m], padded
    __shared__ float Xs[32][128];   // [k][n]

    const int b  = blockIdx.y;
    const int n0 = blockIdx.x * 128;
    const float* Xb = X + (size_t)b * C_ * N_;
    float* Y = which ? g_k : g_q;

    const int tid = threadIdx.x;
    const int tx = tid & 15;    // n
    const int ty = tid >> 4;    // m

    float acc[4][8];
#pragma unroll
    for (int i = 0; i < 4; i++)
#pragma unroll
        for (int j = 0; j < 8; j++) acc[i][j] = 0.f;

    for (int k0 = 0; k0 < C_; k0 += 32) {
#pragma unroll
        for (int r = 0; r < 8; r++) {           // 64x32 = 2048
            int idx = tid + r * 256;
            int m = idx >> 5, kk = idx & 31;
            Ws[kk][m] = W[(size_t)m * C_ + k0 + kk];
        }
#pragma unroll
        for (int r = 0; r < 16; r++) {          // 32x128 = 4096
            int idx = tid + r * 256;
            int kk = idx >> 7, n = idx & 127;
            Xs[kk][n] = Xb[(size_t)(k0 + kk) * N_ + n0 + n];
        }
        __syncthreads();
#pragma unroll
        for (int kk = 0; kk < 32; kk++) {
            float a[4], bb[8];
#pragma unroll
            for (int i = 0; i < 4; i++) a[i] = Ws[kk][ty * 4 + i];
            LD8(bb, &Xs[kk][tx * 8]);
#pragma unroll
            for (int i = 0; i < 4; i++)
#pragma unroll
                for (int j = 0; j < 8; j++) acc[i][j] += a[i] * bb[j];
        }
        __syncthreads();
    }

#pragma unroll
    for (int i = 0; i < 4; i++) {
        int m = ty * 4 + i;
        float bv = bias[m];
        float* yp = Y + ((size_t)b * CQ_ + m) * N_ + n0 + tx * 8;
        float4 v0 = make_float4(acc[i][0]+bv, acc[i][1]+bv, acc[i][2]+bv, acc[i][3]+bv);
        float4 v1 = make_float4(acc[i][4]+bv, acc[i][5]+bv, acc[i][6]+bv, acc[i][7]+bv);
        *(float4*)(yp)     = v0;
        *(float4*)(yp + 4) = v1;
    }
}

// ---------------------------------------------------------------------------
// V projection (fused): V[b][c][n] = Wvs@xs + Wvt@xt + (bvs+bvt)
// BM=128, BN=128, BK=16, 256 threads, 8x8 microtile
// ---------------------------------------------------------------------------
__global__ __launch_bounds__(256) void v_proj_kernel(
    const float* __restrict__ W1, const float* __restrict__ W2,
    const float* __restrict__ b1, const float* __restrict__ b2,
    const float* __restrict__ X1, const float* __restrict__ X2)
{
    __shared__ float W1s[16][132], W2s[16][132];   // [k][c], padded
    __shared__ float X1s[16][128], X2s[16][128];   // [k][n]

    const int b  = blockIdx.z;
    const int c0 = blockIdx.y * 128;
    const int n0 = blockIdx.x * 128;
    const float* X1b = X1 + (size_t)b * C_ * N_;
    const float* X2b = X2 + (size_t)b * C_ * N_;

    const int tid = threadIdx.x;
    const int tx = tid & 15;    // n
    const int ty = tid >> 4;    // c

    float acc[8][8];
#pragma unroll
    for (int i = 0; i < 8; i++)
#pragma unroll
        for (int j = 0; j < 8; j++) acc[i][j] = 0.f;

    for (int k0 = 0; k0 < C_; k0 += 16) {
#pragma unroll
        for (int r = 0; r < 8; r++) {           // 128x16 = 2048 each
            int idx = tid + r * 256;
            int m = idx >> 4, kk = idx & 15;
            W1s[kk][m] = W1[(size_t)(c0 + m) * C_ + k0 + kk];
            W2s[kk][m] = W2[(size_t)(c0 + m) * C_ + k0 + kk];
        }
#pragma unroll
        for (int r = 0; r < 8; r++) {           // 16x128 = 2048 each
            int idx = tid + r * 256;
            int kk = idx >> 7, n = idx & 127;
            X1s[kk][n] = X1b[(size_t)(k0 + kk) * N_ + n0 + n];
            X2s[kk][n] = X2b[(size_t)(k0 + kk) * N_ + n0 + n];
        }
        __syncthreads();
#pragma unroll
        for (int kk = 0; kk < 16; kk++) {
            float a1[8], a2[8], bb1[8], bb2[8];
            LD8(a1,  &W1s[kk][ty * 8]);
            LD8(a2,  &W2s[kk][ty * 8]);
            LD8(bb1, &X1s[kk][tx * 8]);
            LD8(bb2, &X2s[kk][tx * 8]);
#pragma unroll
            for (int i = 0; i < 8; i++)
#pragma unroll
                for (int j = 0; j < 8; j++)
                    acc[i][j] += a1[i] * bb1[j] + a2[i] * bb2[j];
        }
        __syncthreads();
    }

#pragma unroll
    for (int i = 0; i < 8; i++) {
        int c = c0 + ty * 8 + i;
        float bv = b1[c] + b2[c];
        float* yp = g_v + ((size_t)b * C_ + c) * N_ + n0 + tx * 8;
        float4 v0 = make_float4(acc[i][0]+bv, acc[i][1]+bv, acc[i][2]+bv, acc[i][3]+bv);
        float4 v1 = make_float4(acc[i][4]+bv, acc[i][5]+bv, acc[i][6]+bv, acc[i][7]+bv);
        *(float4*)(yp)     = v0;
        *(float4*)(yp + 4) = v1;
    }
}

// ---------------------------------------------------------------------------
// Energy: E[b][i][j] = SCALE * sum_q Q[b][q][i] * K[b][q][j]
// BM=BN=128 (i,j), K = 64 (2 chunks of 32), 256 threads, 8x8 microtile
// ---------------------------------------------------------------------------
__global__ __launch_bounds__(256) void energy_kernel()
{
    __shared__ float Qs[32][128];   // [q][i]
    __shared__ float Ks[32][128];   // [q][j]

    const int b  = blockIdx.z;
    const int i0 = blockIdx.y * 128;
    const int j0 = blockIdx.x * 128;
    const float* Qb = g_q + (size_t)b * CQ_ * N_;
    const float* Kb = g_k + (size_t)b * CQ_ * N_;

    const int tid = threadIdx.x;
    const int tx = tid & 15;    // j
    const int ty = tid >> 4;    // i

    float acc[8][8];
#pragma unroll
    for (int i = 0; i < 8; i++)
#pragma unroll
        for (int j = 0; j < 8; j++) acc[i][j] = 0.f;

    for (int k0 = 0; k0 < CQ_; k0 += 32) {
#pragma unroll
        for (int r = 0; r < 16; r++) {          // 32x128 = 4096
            int idx = tid + r * 256;
            int kk = idx >> 7, col = idx & 127;
            Qs[kk][col] = Qb[(size_t)(k0 + kk) * N_ + i0 + col];
            Ks[kk][col] = Kb[(size_t)(k0 + kk) * N_ + j0 + col];
        }
        __syncthreads();
#pragma unroll
        for (int kk = 0; kk < 32; kk++) {
            float a[8], bb[8];
            LD8(a,  &Qs[kk][ty * 8]);
            LD8(bb, &Ks[kk][tx * 8]);
#pragma unroll
            for (int i = 0; i < 8; i++)
#pragma unroll
                for (int j = 0; j < 8; j++) acc[i][j] += a[i] * bb[j];
        }
        __syncthreads();
    }

#pragma unroll
    for (int i = 0; i < 8; i++) {
        float* pp = g_p + ((size_t)b * N_ + i0 + ty * 8 + i) * N_ + j0 + tx * 8;
        float4 v0 = make_float4(acc[i][0]*SCALE_, acc[i][1]*SCALE_, acc[i][2]*SCALE_, acc[i][3]*SCALE_);
        float4 v1 = make_float4(acc[i][4]*SCALE_, acc[i][5]*SCALE_, acc[i][6]*SCALE_, acc[i][7]*SCALE_);
        *(float4*)(pp)     = v0;
        *(float4*)(pp + 4) = v1;
    }
}

// ---------------------------------------------------------------------------
// Softmax (unnormalized): p <- exp(p - rowmax); rowsum stored for epilogue
// One block per (b,i) row of 4096, 256 threads, 16 values/thread in regs
// ---------------------------------------------------------------------------
__global__ __launch_bounds__(256) void softmax_kernel()
{
    __shared__ float red[256];
    const size_t row = blockIdx.x;
    float* p = g_p + row * N_;
    const int tid = threadIdx.x;

    float v[16];
    float m = -1e30f;
#pragma unroll
    for (int t = 0; t < 16; t++) {
        v[t] = p[tid + t * 256];
        m = fmaxf(m, v[t]);
    }
    red[tid] = m; __syncthreads();
    for (int s = 128; s > 0; s >>= 1) {
        if (tid < s) red[tid] = fmaxf(red[tid], red[tid + s]);
        __syncthreads();
    }
    m = red[0];
    __syncthreads();

    float s = 0.f;
#pragma unroll
    for (int t = 0; t < 16; t++) {
        float e = expf(v[t] - m);
        p[tid + t * 256] = e;
        s += e;
    }
    red[tid] = s; __syncthreads();
    for (int st = 128; st > 0; st >>= 1) {
        if (tid < st) red[tid] += red[tid + st];
        __syncthreads();
    }
    if (tid == 0) g_rowsum[row] = red[0];
}

// ---------------------------------------------------------------------------
// Output: out[b][c][i] = (sum_j V[b][c][j] * P[b][i][j]) / rowsum[b][i]
//                        + xs[b][c][i] + xt[b][c][i]
// BM=128 (c), BN=128 (i), BK=32 (j), 256 threads, 8x8 microtile
// ---------------------------------------------------------------------------
__global__ __launch_bounds__(256) void out_kernel(
    const float* __restrict__ xs, const float* __restrict__ xt,
    float* __restrict__ out)
{
    __shared__ float Vs[32][132];   // [j][c], padded
    __shared__ float Ps[32][132];   // [j][i], padded

    const int b  = blockIdx.z;
    const int c0 = blockIdx.y * 128;
    const int i0 = blockIdx.x * 128;
    const float* Vb = g_v + (size_t)b * C_ * N_;
    const float* Pb = g_p + (size_t)b * N_ * N_;

    const int tid = threadIdx.x;
    const int tx = tid & 15;    // i
    const int ty = tid >> 4;    // c

    float acc[8][8];
#pragma unroll
    for (int i = 0; i < 8; i++)
#pragma unroll
        for (int j = 0; j < 8; j++) acc[i][j] = 0.f;

    for (int j0 = 0; j0 < N_; j0 += 32) {
#pragma unroll
        for (int r = 0; r < 16; r++) {          // 128x32 = 4096
            int idx = tid + r * 256;
            int c = idx >> 5, jj = idx & 31;
            Vs[jj][c] = Vb[(size_t)(c0 + c) * N_ + j0 + jj];
        }
#pragma unroll
        for (int r = 0; r < 16; r++) {
            int idx = tid + r * 256;
            int i = idx >> 5, jj = idx & 31;
            Ps[jj][i] = Pb[(size_t)(i0 + i) * N_ + j0 + jj];
        }
        __syncthreads();
#pragma unroll
        for (int kj = 0; kj < 32; kj++) {
            float a[8], bb[8];
            LD8(a,  &Vs[kj][ty * 8]);
            LD8(bb, &Ps[kj][tx * 8]);
#pragma unroll
            for (int i = 0; i < 8; i++)
#pragma unroll
                for (int j = 0; j < 8; j++) acc[i][j] += a[i] * bb[j];
        }
        __syncthreads();
    }

    // per-column 1/rowsum
    float inv[8];
#pragma unroll
    for (int j = 0; j < 8; j++)
        inv[j] = 1.f / g_rowsum[b * N_ + i0 + tx * 8 + j];

#pragma unroll
    for (int i = 0; i < 8; i++) {
        int c = c0 + ty * 8 + i;
        size_t base = ((size_t)b * C_ + c) * N_ + i0 + tx * 8;
        const float4 xs0 = *(const float4*)(xs + base);
        const float4 xs1 = *(const float4*)(xs + base + 4);
        const float4 xt0 = *(const float4*)(xt + base);
        const float4 xt1 = *(const float4*)(xt + base + 4);
        float4 v0, v1;
        v0.x = acc[i][0]*inv[0] + xs0.x + xt0.x;
        v0.y = acc[i][1]*inv[1] + xs0.y + xt0.y;
        v0.z = acc[i][2]*inv[2] + xs0.z + xt0.z;
        v0.w = acc[i][3]*inv[3] + xs0.w + xt0.w;
        v1.x = acc[i][4]*inv[4] + xs1.x + xt1.x;
        v1.y = acc[i][5]*inv[5] + xs1.y + xt1.y;
        v1.z = acc[i][6]*inv[6] + xs1.z + xt1.z;
        v1.w = acc[i][7]*inv[7] + xs1.w + xt1.w;
        *(float4*)(out + base)     = v0;
        *(float4*)(out + base + 4) = v1;
    }
}

// ---------------------------------------------------------------------------
extern "C" void kernel_launch(void* const* d_in, const int* in_sizes, int n_in,
                              void* d_out, int out_size)
{
    const float* xs  = (const float*)d_in[0];
    const float* xt  = (const float*)d_in[1];
    const float* Wq  = (const float*)d_in[2];
    const float* bq  = (const float*)d_in[3];
    const float* Wk  = (const float*)d_in[4];
    const float* bk  = (const float*)d_in[5];
    const float* Wvs = (const float*)d_in[6];
    const float* bvs = (const float*)d_in[7];
    const float* Wvt = (const float*)d_in[8];
    const float* bvt = (const float*)d_in[9];
    float* out = (float*)d_out;

    qk_proj_kernel<<<dim3(N_ / 128, B_), 256>>>(Wq, bq, xs, 0);
    qk_proj_kernel<<<dim3(N_ / 128, B_), 256>>>(Wk, bk, xt, 1);
    v_proj_kernel<<<dim3(N_ / 128, C_ / 128, B_), 256>>>(Wvs, Wvt, bvs, bvt, xs, xt);
    energy_kernel<<<dim3(N_ / 128, N_ / 128, B_), 256>>>();
    softmax_kernel<<<B_ * N_, 256>>>();
    out_kernel<<<dim3(N_ / 128, C_ / 128, B_), 256>>>(xs, xt, out);
}

// round 3
// speedup vs baseline: 1.7652x; 1.7652x over previous
#include <cuda_runtime.h>
#include <cuda_bf16.h>
#include <cstdint>
#include <cstddef>

#define B_   4
#define C_   512
#define N_   4096
#define CQ_  64
#define SCALE_ 0.125f   // (C/8)^-0.5

// ---------------- device scratch ----------
__device__ float g_q[B_ * CQ_ * N_];
__device__ float g_k[B_ * CQ_ * N_];
__device__ float g_e[(size_t)B_ * N_ * N_];              // energy fp32
__device__ __nv_bfloat16 g_vh[(size_t)B_ * C_ * N_];     // V hi/lo bf16
__device__ __nv_bfloat16 g_vl[(size_t)B_ * C_ * N_];
__device__ __nv_bfloat16 g_ph[(size_t)B_ * N_ * N_];     // exp(E) hi/lo bf16
__device__ __nv_bfloat16 g_pl[(size_t)B_ * N_ * N_];
__device__ float g_rowsum[B_ * N_];

#define LD8(dst, ptr)                                              \
    do {                                                           \
        float4 _u0 = *(const float4*)((ptr));                      \
        float4 _u1 = *(const float4*)((ptr) + 4);                  \
        (dst)[0]=_u0.x; (dst)[1]=_u0.y; (dst)[2]=_u0.z; (dst)[3]=_u0.w; \
        (dst)[4]=_u1.x; (dst)[5]=_u1.y; (dst)[6]=_u1.z; (dst)[7]=_u1.w; \
    } while (0)

// ====================== helpers ======================
__device__ __forceinline__ uint32_t smem_u32(const void* p) {
    uint32_t a;
    asm("{ .reg .u64 t; cvta.to.shared.u64 t, %1; cvt.u32.u64 %0, t; }" : "=r"(a) : "l"(p));
    return a;
}
__device__ __forceinline__ void cp16(uint32_t dst, const void* src) {
    asm volatile("cp.async.cg.shared.global [%0], [%1], 16;" :: "r"(dst), "l"(src));
}
__device__ __forceinline__ void ldm_x4(uint32_t* r, uint32_t addr) {
    asm volatile("ldmatrix.sync.aligned.m8n8.x4.shared.b16 {%0,%1,%2,%3}, [%4];"
        : "=r"(r[0]), "=r"(r[1]), "=r"(r[2]), "=r"(r[3]) : "r"(addr));
}
__device__ __forceinline__ void mma16816(float* c, const uint32_t* a, uint32_t b0, uint32_t b1) {
    asm volatile(
        "mma.sync.aligned.m16n8k16.row.col.f32.bf16.bf16.f32 "
        "{%0,%1,%2,%3}, {%4,%5,%6,%7}, {%8,%9}, {%0,%1,%2,%3};"
        : "+f"(c[0]), "+f"(c[1]), "+f"(c[2]), "+f"(c[3])
        : "r"(a[0]), "r"(a[1]), "r"(a[2]), "r"(a[3]), "r"(b0), "r"(b1));
}
__device__ __forceinline__ void split_bf16(float v, __nv_bfloat16& h, __nv_bfloat16& l) {
    h = __float2bfloat16(v);
    l = __float2bfloat16(v - __bfloat162float(h));
}

// ---------------------------------------------------------------------------
// Q/K projection (fp32)
// ---------------------------------------------------------------------------
__global__ __launch_bounds__(256) void qk_proj_kernel(
    const float* __restrict__ W, const float* __restrict__ bias,
    const float* __restrict__ X, int which)
{
    __shared__ float Ws[32][68];
    __shared__ float Xs[32][128];

    const int b  = blockIdx.y;
    const int n0 = blockIdx.x * 128;
    const float* Xb = X + (size_t)b * C_ * N_;
    float* Y = which ? g_k : g_q;

    const int tid = threadIdx.x;
    const int tx = tid & 15;
    const int ty = tid >> 4;

    float acc[4][8];
#pragma unroll
    for (int i = 0; i < 4; i++)
#pragma unroll
        for (int j = 0; j < 8; j++) acc[i][j] = 0.f;

    for (int k0 = 0; k0 < C_; k0 += 32) {
#pragma unroll
        for (int r = 0; r < 8; r++) {
            int idx = tid + r * 256;
            int m = idx >> 5, kk = idx & 31;
            Ws[kk][m] = W[(size_t)m * C_ + k0 + kk];
        }
#pragma unroll
        for (int r = 0; r < 16; r++) {
            int idx = tid + r * 256;
            int kk = idx >> 7, n = idx & 127;
            Xs[kk][n] = Xb[(size_t)(k0 + kk) * N_ + n0 + n];
        }
        __syncthreads();
#pragma unroll
        for (int kk = 0; kk < 32; kk++) {
            float a[4], bb[8];
#pragma unroll
            for (int i = 0; i < 4; i++) a[i] = Ws[kk][ty * 4 + i];
            LD8(bb, &Xs[kk][tx * 8]);
#pragma unroll
            for (int i = 0; i < 4; i++)
#pragma unroll
                for (int j = 0; j < 8; j++) acc[i][j] += a[i] * bb[j];
        }
        __syncthreads();
    }
#pragma unroll
    for (int i = 0; i < 4; i++) {
        int m = ty * 4 + i;
        float bv = bias[m];
        float* yp = Y + ((size_t)b * CQ_ + m) * N_ + n0 + tx * 8;
        float4 v0 = make_float4(acc[i][0]+bv, acc[i][1]+bv, acc[i][2]+bv, acc[i][3]+bv);
        float4 v1 = make_float4(acc[i][4]+bv, acc[i][5]+bv, acc[i][6]+bv, acc[i][7]+bv);
        *(float4*)(yp)     = v0;
        *(float4*)(yp + 4) = v1;
    }
}

// ---------------------------------------------------------------------------
// V projection (fp32 compute) -> bf16 hi/lo outputs
// ---------------------------------------------------------------------------
__global__ __launch_bounds__(256) void v_proj_kernel(
    const float* __restrict__ W1, const float* __restrict__ W2,
    const float* __restrict__ b1, const float* __restrict__ b2,
    const float* __restrict__ X1, const float* __restrict__ X2)
{
    __shared__ float W1s[16][132], W2s[16][132];
    __shared__ float X1s[16][128], X2s[16][128];

    const int b  = blockIdx.z;
    const int c0 = blockIdx.y * 128;
    const int n0 = blockIdx.x * 128;
    const float* X1b = X1 + (size_t)b * C_ * N_;
    const float* X2b = X2 + (size_t)b * C_ * N_;

    const int tid = threadIdx.x;
    const int tx = tid & 15;
    const int ty = tid >> 4;

    float acc[8][8];
#pragma unroll
    for (int i = 0; i < 8; i++)
#pragma unroll
        for (int j = 0; j < 8; j++) acc[i][j] = 0.f;

    for (int k0 = 0; k0 < C_; k0 += 16) {
#pragma unroll
        for (int r = 0; r < 8; r++) {
            int idx = tid + r * 256;
            int m = idx >> 4, kk = idx & 15;
            W1s[kk][m] = W1[(size_t)(c0 + m) * C_ + k0 + kk];
            W2s[kk][m] = W2[(size_t)(c0 + m) * C_ + k0 + kk];
        }
#pragma unroll
        for (int r = 0; r < 8; r++) {
            int idx = tid + r * 256;
            int kk = idx >> 7, n = idx & 127;
            X1s[kk][n] = X1b[(size_t)(k0 + kk) * N_ + n0 + n];
            X2s[kk][n] = X2b[(size_t)(k0 + kk) * N_ + n0 + n];
        }
        __syncthreads();
#pragma unroll
        for (int kk = 0; kk < 16; kk++) {
            float a1[8], a2[8], bb1[8], bb2[8];
            LD8(a1,  &W1s[kk][ty * 8]);
            LD8(a2,  &W2s[kk][ty * 8]);
            LD8(bb1, &X1s[kk][tx * 8]);
            LD8(bb2, &X2s[kk][tx * 8]);
#pragma unroll
            for (int i = 0; i < 8; i++)
#pragma unroll
                for (int j = 0; j < 8; j++)
                    acc[i][j] += a1[i] * bb1[j] + a2[i] * bb2[j];
        }
        __syncthreads();
    }

#pragma unroll
    for (int i = 0; i < 8; i++) {
        int c = c0 + ty * 8 + i;
        float bv = b1[c] + b2[c];
        size_t base = ((size_t)b * C_ + c) * N_ + n0 + tx * 8;
        __nv_bfloat16 h[8], l[8];
#pragma unroll
        for (int j = 0; j < 8; j++) split_bf16(acc[i][j] + bv, h[j], l[j]);
        uint32_t* vhp = (uint32_t*)(g_vh + base);
        uint32_t* vlp = (uint32_t*)(g_vl + base);
#pragma unroll
        for (int p = 0; p < 4; p++) {
            __nv_bfloat162 hh; hh.x = h[2*p]; hh.y = h[2*p+1];
            __nv_bfloat162 ll; ll.x = l[2*p]; ll.y = l[2*p+1];
            vhp[p] = *(uint32_t*)&hh;
            vlp[p] = *(uint32_t*)&ll;
        }
    }
}

// ---------------------------------------------------------------------------
// Energy (fp32): E[b][i][j] = SCALE * sum_q Q[q][i]K[q][j]
// ---------------------------------------------------------------------------
__global__ __launch_bounds__(256) void energy_kernel()
{
    __shared__ float Qs[32][128];
    __shared__ float Ks[32][128];

    const int b  = blockIdx.z;
    const int i0 = blockIdx.y * 128;
    const int j0 = blockIdx.x * 128;
    const float* Qb = g_q + (size_t)b * CQ_ * N_;
    const float* Kb = g_k + (size_t)b * CQ_ * N_;

    const int tid = threadIdx.x;
    const int tx = tid & 15;
    const int ty = tid >> 4;

    float acc[8][8];
#pragma unroll
    for (int i = 0; i < 8; i++)
#pragma unroll
        for (int j = 0; j < 8; j++) acc[i][j] = 0.f;

    for (int k0 = 0; k0 < CQ_; k0 += 32) {
#pragma unroll
        for (int r = 0; r < 16; r++) {
            int idx = tid + r * 256;
            int kk = idx >> 7, col = idx & 127;
            Qs[kk][col] = Qb[(size_t)(k0 + kk) * N_ + i0 + col];
            Ks[kk][col] = Kb[(size_t)(k0 + kk) * N_ + j0 + col];
        }
        __syncthreads();
#pragma unroll
        for (int kk = 0; kk < 32; kk++) {
            float a[8], bb[8];
            LD8(a,  &Qs[kk][ty * 8]);
            LD8(bb, &Ks[kk][tx * 8]);
#pragma unroll
            for (int i = 0; i < 8; i++)
#pragma unroll
                for (int j = 0; j < 8; j++) acc[i][j] += a[i] * bb[j];
        }
        __syncthreads();
    }
#pragma unroll
    for (int i = 0; i < 8; i++) {
        float* pp = g_e + ((size_t)b * N_ + i0 + ty * 8 + i) * N_ + j0 + tx * 8;
        float4 v0 = make_float4(acc[i][0]*SCALE_, acc[i][1]*SCALE_, acc[i][2]*SCALE_, acc[i][3]*SCALE_);
        float4 v1 = make_float4(acc[i][4]*SCALE_, acc[i][5]*SCALE_, acc[i][6]*SCALE_, acc[i][7]*SCALE_);
        *(float4*)(pp)     = v0;
        *(float4*)(pp + 4) = v1;
    }
}

// ---------------------------------------------------------------------------
// Softmax: fp32 E row -> bf16 hi/lo exp values + rowsum
// ---------------------------------------------------------------------------
__global__ __launch_bounds__(256) void softmax_kernel()
{
    __shared__ float red[256];
    const size_t row = blockIdx.x;
    const float* e = g_e + row * N_;
    __nv_bfloat16* pH = g_ph + row * N_;
    __nv_bfloat16* pL = g_pl + row * N_;
    const int tid = threadIdx.x;

    float v[16];
    float m = -1e30f;
#pragma unroll
    for (int t = 0; t < 16; t++) {
        v[t] = e[tid + t * 256];
        m = fmaxf(m, v[t]);
    }
    red[tid] = m; __syncthreads();
    for (int s = 128; s > 0; s >>= 1) {
        if (tid < s) red[tid] = fmaxf(red[tid], red[tid + s]);
        __syncthreads();
    }
    m = red[0];
    __syncthreads();

    float s = 0.f;
#pragma unroll
    for (int t = 0; t < 16; t++) {
        float ev = expf(v[t] - m);
        __nv_bfloat16 h, l;
        split_bf16(ev, h, l);
        pH[tid + t * 256] = h;
        pL[tid + t * 256] = l;
        s += ev;
    }
    red[tid] = s; __syncthreads();
    for (int st = 128; st > 0; st >>= 1) {
        if (tid < st) red[tid] += red[tid + st];
        __syncthreads();
    }
    if (tid == 0) g_rowsum[row] = red[0];
}

// ---------------------------------------------------------------------------
// Output GEMM on mma.sync bf16 (split hi/lo, 3 products):
//   D[c][i] = sum_j V[c][j] * P[i][j]; out = D*inv_rowsum + xs + xt
// CTA: 128(c) x 128(i), KC=64, double-buffered cp.async; 8 warps (4c x 2i)
// ---------------------------------------------------------------------------
#define KC 64
#define NCH (N_ / KC)            // 64
#define ROWB 144                 // bytes per smem row (128 data + 16 pad)
#define AH_OFF 0
#define AL_OFF (128 * ROWB)      // 18432
#define BH_OFF (2 * 128 * ROWB)  // 36864
#define BL_OFF (3 * 128 * ROWB)  // 55296
#define STAGE_BYTES (4 * 128 * ROWB)   // 73728
#define INV_OFF (2 * STAGE_BYTES)      // 147456
#define DSMEM_BYTES (2 * STAGE_BYTES + 1024 + 1024)

__device__ __forceinline__ void load_stage(
    uint32_t sbase, int b, int c0, int i0, int j0, int tid)
{
#pragma unroll
    for (int k = 0; k < 4; k++) {                  // A: 128 rows x 8 chunks of 16B
        int seg = tid + k * 256;
        int row = seg >> 3, ch = seg & 7;
        uint32_t soff = row * ROWB + ch * 16;
        size_t gi = ((size_t)(b * C_ + c0 + row)) * N_ + j0 + ch * 8;
        cp16(sbase + AH_OFF + soff, g_vh + gi);
        cp16(sbase + AL_OFF + soff, g_vl + gi);
    }
#pragma unroll
    for (int k = 0; k < 4; k++) {                  // B: 128 rows x 8 chunks
        int seg = tid + k * 256;
        int row = seg >> 3, ch = seg & 7;
        uint32_t soff = row * ROWB + ch * 16;
        size_t gi = ((size_t)b * N_ + i0 + row) * N_ + j0 + ch * 8;
        cp16(sbase + BH_OFF + soff, g_ph + gi);
        cp16(sbase + BL_OFF + soff, g_pl + gi);
    }
    asm volatile("cp.async.commit_group;" ::: "memory");
}

__global__ __launch_bounds__(256, 1) void out_mma_kernel(
    const float* __restrict__ xs, const float* __restrict__ xt,
    float* __restrict__ out)
{
    extern __shared__ char dsm[];
    uint32_t raw  = smem_u32(dsm);
    uint32_t base = (raw + 1023) & ~1023u;
    float* inv_s  = (float*)(dsm + (base - raw) + INV_OFF);

    const int tid = threadIdx.x;
    const int wid = tid >> 5;
    const int lane = tid & 31;
    const int warp_m = wid & 3;      // c sub-block (32 rows)
    const int warp_n = wid >> 2;     // i sub-block (64 cols)

    const int b  = blockIdx.z;
    const int c0 = blockIdx.x * 128;
    const int i0 = blockIdx.y * 128;

    float acc[2][8][4];
#pragma unroll
    for (int mt = 0; mt < 2; mt++)
#pragma unroll
        for (int t = 0; t < 8; t++)
#pragma unroll
            for (int q = 0; q < 4; q++) acc[mt][t][q] = 0.f;

    load_stage(base,               b, c0, i0, 0,  tid);
    load_stage(base + STAGE_BYTES, b, c0, i0, KC, tid);

    // ldmatrix base addresses (lane-dependent parts)
    const int lrow = lane & 15;            // row within 16
    const int lkh  = (lane >> 4) * 16;     // k-half byte offset

    for (int chk = 0; chk < NCH; chk++) {
        const int st = chk & 1;
        const uint32_t sb = base + st * STAGE_BYTES;
        if (chk == NCH - 1) asm volatile("cp.async.wait_group 0;" ::: "memory");
        else                asm volatile("cp.async.wait_group 1;" ::: "memory");
        __syncthreads();

        const uint32_t a_base = sb + (warp_m * 32 + lrow) * ROWB + lkh;
        const uint32_t b_base = sb + (warp_n * 64 + lrow) * ROWB + lkh;

#pragma unroll
        for (int ks = 0; ks < 4; ks++) {
            const uint32_t koff = ks * 32;   // 16 elems = 32B per k16 step
            uint32_t ah[2][4], al[2][4];
#pragma unroll
            for (int mt = 0; mt < 2; mt++) {
                ldm_x4(ah[mt], a_base + AH_OFF + mt * (16 * ROWB) + koff);
                ldm_x4(al[mt], a_base + (AL_OFF - AH_OFF) + AH_OFF + mt * (16 * ROWB) + koff);
            }
#pragma unroll
            for (int ng = 0; ng < 4; ng++) {
                uint32_t bh[4], bl[4];
                ldm_x4(bh, b_base + BH_OFF + ng * (16 * ROWB) + koff);
                ldm_x4(bl, b_base + BL_OFF + ng * (16 * ROWB) + koff);
#pragma unroll
                for (int mt = 0; mt < 2; mt++) {
                    mma16816(acc[mt][ng*2],   ah[mt], bh[0], bh[2]);
                    mma16816(acc[mt][ng*2],   ah[mt], bl[0], bl[2]);
                    mma16816(acc[mt][ng*2],   al[mt], bh[0], bh[2]);
                    mma16816(acc[mt][ng*2+1], ah[mt], bh[1], bh[3]);
                    mma16816(acc[mt][ng*2+1], ah[mt], bl[1], bl[3]);
                    mma16816(acc[mt][ng*2+1], al[mt], bh[1], bh[3]);
                }
            }
        }
        __syncthreads();
        if (chk + 2 < NCH) load_stage(sb, b, c0, i0, (chk + 2) * KC, tid);
    }

    // stage inv rowsum for this i-tile
    if (tid < 128) inv_s[tid] = 1.f / g_rowsum[b * N_ + i0 + tid];
    __syncthreads();

    const int gp = lane >> 2;      // row group 0-7
    const int tg = lane & 3;       // col pair
#pragma unroll
    for (int mt = 0; mt < 2; mt++) {
        const int c = c0 + warp_m * 32 + mt * 16 + gp;
#pragma unroll
        for (int t = 0; t < 8; t++) {
            const int iloc = warp_n * 64 + t * 8 + tg * 2;
            const float inv0 = inv_s[iloc], inv1 = inv_s[iloc + 1];
            size_t g0 = ((size_t)(b * C_ + c)) * N_ + i0 + iloc;
            size_t g1 = g0 + 8 * (size_t)N_;    // row c+8
            float2 x1 = *(const float2*)(xs + g0);
            float2 x2 = *(const float2*)(xt + g0);
            float2 r0;
            r0.x = acc[mt][t][0] * inv0 + x1.x + x2.x;
            r0.y = acc[mt][t][1] * inv1 + x1.y + x2.y;
            *(float2*)(out + g0) = r0;
            float2 x3 = *(const float2*)(xs + g1);
            float2 x4 = *(const float2*)(xt + g1);
            float2 r1;
            r1.x = acc[mt][t][2] * inv0 + x3.x + x4.x;
            r1.y = acc[mt][t][3] * inv1 + x3.y + x4.y;
            *(float2*)(out + g1) = r1;
        }
    }
}

// ---------------------------------------------------------------------------
extern "C" void kernel_launch(void* const* d_in, const int* in_sizes, int n_in,
                              void* d_out, int out_size)
{
    const float* xs  = (const float*)d_in[0];
    const float* xt  = (const float*)d_in[1];
    const float* Wq  = (const float*)d_in[2];
    const float* bq  = (const float*)d_in[3];
    const float* Wk  = (const float*)d_in[4];
    const float* bk  = (const float*)d_in[5];
    const float* Wvs = (const float*)d_in[6];
    const float* bvs = (const float*)d_in[7];
    const float* Wvt = (const float*)d_in[8];
    const float* bvt = (const float*)d_in[9];
    float* out = (float*)d_out;

    cudaFuncSetAttribute(out_mma_kernel, cudaFuncAttributeMaxDynamicSharedMemorySize, DSMEM_BYTES);

    qk_proj_kernel<<<dim3(N_ / 128, B_), 256>>>(Wq, bq, xs, 0);
    qk_proj_kernel<<<dim3(N_ / 128, B_), 256>>>(Wk, bk, xt, 1);
    v_proj_kernel<<<dim3(N_ / 128, C_ / 128, B_), 256>>>(Wvs, Wvt, bvs, bvt, xs, xt);
    energy_kernel<<<dim3(N_ / 128, N_ / 128, B_), 256>>>();
    softmax_kernel<<<B_ * N_, 256>>>();
    out_mma_kernel<<<dim3(C_ / 128, N_ / 128, B_), 256, DSMEM_BYTES>>>(xs, xt, out);
}

// round 4
// speedup vs baseline: 2.7687x; 1.5685x over previous
#include <cuda_runtime.h>
#include <cuda_bf16.h>
#include <cstdint>
#include <cstddef>

#define B_   4
#define C_   512
#define N_   4096
#define CQ_  64
#define SCALE_ 0.125f   // (C/8)^-0.5

// ---------------- device scratch (bf16 hi/lo pairs) ----------
__device__ __nv_bfloat16 g_qh[B_ * CQ_ * N_], g_ql[B_ * CQ_ * N_];   // [b][q][n]
__device__ __nv_bfloat16 g_kh[B_ * CQ_ * N_], g_kl[B_ * CQ_ * N_];
__device__ __nv_bfloat16 g_vh[(size_t)B_ * C_ * N_], g_vl[(size_t)B_ * C_ * N_];   // [b][c][n]
__device__ __nv_bfloat16 g_ph[(size_t)B_ * N_ * N_], g_pl[(size_t)B_ * N_ * N_];   // exp(E) [b][i][j]
__device__ __nv_bfloat16 g_xsh[(size_t)B_ * C_ * N_], g_xsl[(size_t)B_ * C_ * N_]; // x splits
__device__ __nv_bfloat16 g_xth[(size_t)B_ * C_ * N_], g_xtl[(size_t)B_ * C_ * N_];
__device__ __nv_bfloat16 g_wsh[C_ * C_], g_wsl[C_ * C_];             // Wvs/Wvt splits [c][k]
__device__ __nv_bfloat16 g_wth[C_ * C_], g_wtl[C_ * C_];
__device__ float g_psum[B_ * 32 * N_];                               // [b][jt][i]
__device__ float g_inv[B_ * N_];

#define LD8(dst, ptr)                                              \
    do {                                                           \
        float4 _u0 = *(const float4*)((ptr));                      \
        float4 _u1 = *(const float4*)((ptr) + 4);                  \
        (dst)[0]=_u0.x; (dst)[1]=_u0.y; (dst)[2]=_u0.z; (dst)[3]=_u0.w; \
        (dst)[4]=_u1.x; (dst)[5]=_u1.y; (dst)[6]=_u1.z; (dst)[7]=_u1.w; \
    } while (0)

// ====================== helpers ======================
__device__ __forceinline__ uint32_t smem_u32(const void* p) {
    uint32_t a;
    asm("{ .reg .u64 t; cvta.to.shared.u64 t, %1; cvt.u32.u64 %0, t; }" : "=r"(a) : "l"(p));
    return a;
}
__device__ __forceinline__ void cp16(uint32_t dst, const void* src) {
    asm volatile("cp.async.cg.shared.global [%0], [%1], 16;" :: "r"(dst), "l"(src));
}
#define CP_COMMIT() asm volatile("cp.async.commit_group;" ::: "memory")
#define CP_WAIT(n)  asm volatile("cp.async.wait_group %0;" :: "n"(n) : "memory")
__device__ __forceinline__ void ldm_x4(uint32_t* r, uint32_t addr) {
    asm volatile("ldmatrix.sync.aligned.m8n8.x4.shared.b16 {%0,%1,%2,%3}, [%4];"
        : "=r"(r[0]), "=r"(r[1]), "=r"(r[2]), "=r"(r[3]) : "r"(addr));
}
__device__ __forceinline__ void ldm_x4t(uint32_t* r, uint32_t addr) {
    asm volatile("ldmatrix.sync.aligned.m8n8.x4.trans.shared.b16 {%0,%1,%2,%3}, [%4];"
        : "=r"(r[0]), "=r"(r[1]), "=r"(r[2]), "=r"(r[3]) : "r"(addr));
}
__device__ __forceinline__ void mma16816(float* c, const uint32_t* a, uint32_t b0, uint32_t b1) {
    asm volatile(
        "mma.sync.aligned.m16n8k16.row.col.f32.bf16.bf16.f32 "
        "{%0,%1,%2,%3}, {%4,%5,%6,%7}, {%8,%9}, {%0,%1,%2,%3};"
        : "+f"(c[0]), "+f"(c[1]), "+f"(c[2]), "+f"(c[3])
        : "r"(a[0]), "r"(a[1]), "r"(a[2]), "r"(a[3]), "r"(b0), "r"(b1));
}
__device__ __forceinline__ void split_bf16(float v, __nv_bfloat16& h, __nv_bfloat16& l) {
    h = __float2bfloat16(v);
    l = __float2bfloat16(v - __bfloat162float(h));
}
__device__ __forceinline__ uint32_t pack2(__nv_bfloat16 a, __nv_bfloat16 b) {
    __nv_bfloat162 t; t.x = a; t.y = b;
    return *(uint32_t*)&t;
}

// ---------------------------------------------------------------------------
// Prep: split fp32 tensors into bf16 hi/lo
// ---------------------------------------------------------------------------
__global__ __launch_bounds__(256) void x_split_kernel(
    const float* __restrict__ xs, const float* __restrict__ xt)
{
    const size_t idx4 = ((size_t)blockIdx.x * 256 + threadIdx.x) * 4;
    const float* src = blockIdx.y ? xt : xs;
    __nv_bfloat16* oh = blockIdx.y ? g_xth : g_xsh;
    __nv_bfloat16* ol = blockIdx.y ? g_xtl : g_xsl;
    float4 v = *(const float4*)(src + idx4);
    __nv_bfloat16 h0,l0,h1,l1,h2,l2,h3,l3;
    split_bf16(v.x,h0,l0); split_bf16(v.y,h1,l1);
    split_bf16(v.z,h2,l2); split_bf16(v.w,h3,l3);
    uint32_t* ph = (uint32_t*)(oh + idx4);
    uint32_t* pl = (uint32_t*)(ol + idx4);
    ph[0] = pack2(h0,h1); ph[1] = pack2(h2,h3);
    pl[0] = pack2(l0,l1); pl[1] = pack2(l2,l3);
}

__global__ __launch_bounds__(256) void w_split_kernel(
    const float* __restrict__ Wvs, const float* __restrict__ Wvt)
{
    const size_t idx4 = ((size_t)blockIdx.x * 256 + threadIdx.x) * 4;
    const float* src = blockIdx.y ? Wvt : Wvs;
    __nv_bfloat16* oh = blockIdx.y ? g_wth : g_wsh;
    __nv_bfloat16* ol = blockIdx.y ? g_wtl : g_wsl;
    float4 v = *(const float4*)(src + idx4);
    __nv_bfloat16 h0,l0,h1,l1,h2,l2,h3,l3;
    split_bf16(v.x,h0,l0); split_bf16(v.y,h1,l1);
    split_bf16(v.z,h2,l2); split_bf16(v.w,h3,l3);
    uint32_t* ph = (uint32_t*)(oh + idx4);
    uint32_t* pl = (uint32_t*)(ol + idx4);
    ph[0] = pack2(h0,h1); ph[1] = pack2(h2,h3);
    pl[0] = pack2(l0,l1); pl[1] = pack2(l2,l3);
}

// ---------------------------------------------------------------------------
// Q/K projection fp32 -> bf16 hi/lo outputs  [b][q][n]
// ---------------------------------------------------------------------------
__global__ __launch_bounds__(256) void qk_proj_kernel(
    const float* __restrict__ W, const float* __restrict__ bias,
    const float* __restrict__ X, int which)
{
    __shared__ float Ws[32][68];
    __shared__ float Xs[32][128];

    const int b  = blockIdx.y;
    const int n0 = blockIdx.x * 128;
    const float* Xb = X + (size_t)b * C_ * N_;
    __nv_bfloat16* Yh = which ? g_kh : g_qh;
    __nv_bfloat16* Yl = which ? g_kl : g_ql;

    const int tid = threadIdx.x;
    const int tx = tid & 15;
    const int ty = tid >> 4;

    float acc[4][8];
#pragma unroll
    for (int i = 0; i < 4; i++)
#pragma unroll
        for (int j = 0; j < 8; j++) acc[i][j] = 0.f;

    for (int k0 = 0; k0 < C_; k0 += 32) {
#pragma unroll
        for (int r = 0; r < 8; r++) {
            int idx = tid + r * 256;
            int m = idx >> 5, kk = idx & 31;
            Ws[kk][m] = W[(size_t)m * C_ + k0 + kk];
        }
#pragma unroll
        for (int r = 0; r < 16; r++) {
            int idx = tid + r * 256;
            int kk = idx >> 7, n = idx & 127;
            Xs[kk][n] = Xb[(size_t)(k0 + kk) * N_ + n0 + n];
        }
        __syncthreads();
#pragma unroll
        for (int kk = 0; kk < 32; kk++) {
            float a[4], bb[8];
#pragma unroll
            for (int i = 0; i < 4; i++) a[i] = Ws[kk][ty * 4 + i];
            LD8(bb, &Xs[kk][tx * 8]);
#pragma unroll
            for (int i = 0; i < 4; i++)
#pragma unroll
                for (int j = 0; j < 8; j++) acc[i][j] += a[i] * bb[j];
        }
        __syncthreads();
    }
#pragma unroll
    for (int i = 0; i < 4; i++) {
        int m = ty * 4 + i;
        float bv = bias[m];
        size_t base = ((size_t)b * CQ_ + m) * N_ + n0 + tx * 8;
        uint32_t* yh = (uint32_t*)(Yh + base);
        uint32_t* yl = (uint32_t*)(Yl + base);
#pragma unroll
        for (int p = 0; p < 4; p++) {
            __nv_bfloat16 h0,l0,h1,l1;
            split_bf16(acc[i][2*p] + bv, h0, l0);
            split_bf16(acc[i][2*p+1] + bv, h1, l1);
            yh[p] = pack2(h0, h1);
            yl[p] = pack2(l0, l1);
        }
    }
}

// ---------------------------------------------------------------------------
// V projection on mma.sync: V = Wvs@xs + Wvt@xt + bias  -> bf16 hi/lo
// CTA 128c x 128n, KC=32, 2 stages. Warps 4c x 2n.
// ---------------------------------------------------------------------------
#define VP_AROW 80                    // 64B + 16 pad
#define VP_BROW 272                   // 256B + 16 pad
#define VP_AMAT (128 * VP_AROW)       // 10240
#define VP_BMAT (32 * VP_BROW)        // 8704
#define VP_WSH 0
#define VP_WSL VP_AMAT
#define VP_WTH (2 * VP_AMAT)
#define VP_WTL (3 * VP_AMAT)
#define VP_XSH (4 * VP_AMAT)
#define VP_XSL (4 * VP_AMAT + VP_BMAT)
#define VP_XTH (4 * VP_AMAT + 2 * VP_BMAT)
#define VP_XTL (4 * VP_AMAT + 3 * VP_BMAT)
#define VP_STAGE (4 * VP_AMAT + 4 * VP_BMAT)   // 75776
#define VP_SMEM (2 * VP_STAGE + 1024)

__device__ __forceinline__ void vp_load_stage(uint32_t sb, int b, int c0, int n0, int k0, int tid)
{
#pragma unroll
    for (int k = 0; k < 8; k++) {          // A: 4 mats x 128 rows x 4 chunks
        int idx = tid + k * 256;
        int mat = idx >> 9, rem = idx & 511;
        int r = rem >> 2, ch = rem & 3;
        const __nv_bfloat16* src;
        switch (mat) {
            case 0: src = g_wsh; break;
            case 1: src = g_wsl; break;
            case 2: src = g_wth; break;
            default: src = g_wtl; break;
        }
        cp16(sb + mat * VP_AMAT + r * VP_AROW + ch * 16,
             src + (size_t)(c0 + r) * C_ + k0 + ch * 8);
    }
#pragma unroll
    for (int k = 0; k < 8; k++) {          // B: 4 mats x 32 rows x 16 chunks
        int idx = tid + k * 256;
        int mat = idx >> 9, rem = idx & 511;
        int r = rem >> 4, ch = rem & 15;
        const __nv_bfloat16* src;
        switch (mat) {
            case 0: src = g_xsh; break;
            case 1: src = g_xsl; break;
            case 2: src = g_xth; break;
            default: src = g_xtl; break;
        }
        cp16(sb + 4 * VP_AMAT + mat * VP_BMAT + r * VP_BROW + ch * 16,
             src + ((size_t)b * C_ + k0 + r) * N_ + n0 + ch * 8);
    }
    CP_COMMIT();
}

__global__ __launch_bounds__(256, 1) void v_proj_mma_kernel(
    const float* __restrict__ bvs, const float* __restrict__ bvt)
{
    extern __shared__ char dsm[];
    uint32_t raw  = smem_u32(dsm);
    uint32_t base = (raw + 1023) & ~1023u;

    const int tid = threadIdx.x;
    const int lane = tid & 31;
    const int wid = tid >> 5;
    const int warp_m = wid & 3;      // c: 32 rows
    const int warp_n = wid >> 2;     // n: 64 cols

    const int b  = blockIdx.z;
    const int c0 = blockIdx.y * 128;
    const int n0 = blockIdx.x * 128;

    float acc[2][8][4];
#pragma unroll
    for (int mt = 0; mt < 2; mt++)
#pragma unroll
        for (int t = 0; t < 8; t++)
#pragma unroll
            for (int q = 0; q < 4; q++) acc[mt][t][q] = 0.f;

    vp_load_stage(base,            b, c0, n0, 0,  tid);
    vp_load_stage(base + VP_STAGE, b, c0, n0, 32, tid);

    // A (non-trans): row = warp_m*32 + mt*16 + (lane&15), colb = (lane>>4)*16 + ks*32
    const uint32_t a_lrow = (uint32_t)(warp_m * 32 + (lane & 15));
    const uint32_t a_lcol = (uint32_t)((lane >> 4) * 16);
    // B (trans from [k][n]): row = ks*16 + (lane&7)+(lane&8), colb = (warp_n*64 + ((lane>>4)&1)*8 + ng*16)*2
    const uint32_t b_lrow = (uint32_t)((lane & 7) | (lane & 8));
    const uint32_t b_lcol = (uint32_t)((warp_n * 64 + ((lane >> 4) & 1) * 8) * 2);

    for (int chk = 0; chk < 16; chk++) {
        const uint32_t sb = base + (chk & 1) * VP_STAGE;
        if (chk == 15) CP_WAIT(0); else CP_WAIT(1);
        __syncthreads();

#pragma unroll
        for (int ks = 0; ks < 2; ks++) {
            uint32_t wsh[2][4], wsl[2][4], wth[2][4], wtl[2][4];
#pragma unroll
            for (int mt = 0; mt < 2; mt++) {
                uint32_t aoff = (a_lrow + mt * 16) * VP_AROW + a_lcol + ks * 32;
                ldm_x4(wsh[mt], sb + VP_WSH + aoff);
                ldm_x4(wsl[mt], sb + VP_WSL + aoff);
                ldm_x4(wth[mt], sb + VP_WTH + aoff);
                ldm_x4(wtl[mt], sb + VP_WTL + aoff);
            }
#pragma unroll
            for (int ng = 0; ng < 4; ng++) {
                uint32_t boff = (b_lrow + ks * 16) * VP_BROW + b_lcol + ng * 32;
                uint32_t xsh[4], xsl[4], xth[4], xtl[4];
                ldm_x4t(xsh, sb + VP_XSH + boff);
                ldm_x4t(xsl, sb + VP_XSL + boff);
                ldm_x4t(xth, sb + VP_XTH + boff);
                ldm_x4t(xtl, sb + VP_XTL + boff);
#pragma unroll
                for (int mt = 0; mt < 2; mt++)
#pragma unroll
                    for (int sub = 0; sub < 2; sub++) {
                        float* a = acc[mt][ng * 2 + sub];
                        uint32_t s0 = sub ? xsh[2] : xsh[0], s1 = sub ? xsh[3] : xsh[1];
                        uint32_t sl0 = sub ? xsl[2] : xsl[0], sl1 = sub ? xsl[3] : xsl[1];
                        uint32_t t0 = sub ? xth[2] : xth[0], t1 = sub ? xth[3] : xth[1];
                        uint32_t tl0 = sub ? xtl[2] : xtl[0], tl1 = sub ? xtl[3] : xtl[1];
                        mma16816(a, wsh[mt], s0, s1);
                        mma16816(a, wsh[mt], sl0, sl1);
                        mma16816(a, wsl[mt], s0, s1);
                        mma16816(a, wth[mt], t0, t1);
                        mma16816(a, wth[mt], tl0, tl1);
                        mma16816(a, wtl[mt], t0, t1);
                    }
            }
        }
        __syncthreads();
        if (chk + 2 < 16) vp_load_stage(sb, b, c0, n0, (chk + 2) * 32, tid);
    }

    const int gp = lane >> 2, tg = lane & 3;
#pragma unroll
    for (int mt = 0; mt < 2; mt++) {
        const int r0 = c0 + warp_m * 32 + mt * 16 + gp;
        const float bv0 = bvs[r0] + bvt[r0];
        const float bv1 = bvs[r0 + 8] + bvt[r0 + 8];
#pragma unroll
        for (int t = 0; t < 8; t++) {
            const int nc = n0 + warp_n * 64 + t * 8 + tg * 2;
            size_t i0 = ((size_t)b * C_ + r0) * N_ + nc;
            size_t i1 = i0 + 8 * (size_t)N_;
            __nv_bfloat16 h0,l0,h1,l1;
            split_bf16(acc[mt][t][0] + bv0, h0, l0);
            split_bf16(acc[mt][t][1] + bv0, h1, l1);
            *(uint32_t*)(g_vh + i0) = pack2(h0, h1);
            *(uint32_t*)(g_vl + i0) = pack2(l0, l1);
            split_bf16(acc[mt][t][2] + bv1, h0, l0);
            split_bf16(acc[mt][t][3] + bv1, h1, l1);
            *(uint32_t*)(g_vh + i1) = pack2(h0, h1);
            *(uint32_t*)(g_vl + i1) = pack2(l0, l1);
        }
    }
}

// ---------------------------------------------------------------------------
// Energy + exp (fused): P = exp(SCALE * Q^T K) -> bf16 hi/lo + partial rowsums
// CTA 128i x 128j; K = CQ = 64. Warps 4i x 2j.
// ---------------------------------------------------------------------------
#define EN_ROW 272                    // 256B + 16
#define EN_MAT (64 * EN_ROW)          // 17408
#define EN_QH 0
#define EN_QL EN_MAT
#define EN_KH (2 * EN_MAT)
#define EN_KL (3 * EN_MAT)
#define EN_PS (4 * EN_MAT)            // 69632: 2 x 128 floats
#define EN_SMEM (4 * EN_MAT + 1024 + 1024)

__global__ __launch_bounds__(256, 1) void energy_exp_kernel()
{
    extern __shared__ char dsm[];
    uint32_t raw  = smem_u32(dsm);
    uint32_t base = (raw + 1023) & ~1023u;
    float* ps = (float*)(dsm + (base - raw) + EN_PS);

    const int tid = threadIdx.x;
    const int lane = tid & 31;
    const int wid = tid >> 5;
    const int warp_m = wid & 3;      // i
    const int warp_n = wid >> 2;     // j

    const int b  = blockIdx.z;
    const int i0 = blockIdx.y * 128;
    const int jt = blockIdx.x;
    const int j0 = jt * 128;

    // load Q,K tiles: 4 mats x 64 rows x 16 chunks
#pragma unroll
    for (int k = 0; k < 16; k++) {
        int idx = tid + k * 256;
        int mat = idx >> 10, rem = idx & 1023;
        int r = rem >> 4, ch = rem & 15;
        const __nv_bfloat16* src;
        int col;
        switch (mat) {
            case 0: src = g_qh; col = i0; break;
            case 1: src = g_ql; col = i0; break;
            case 2: src = g_kh; col = j0; break;
            default: src = g_kl; col = j0; break;
        }
        cp16(base + mat * EN_MAT + r * EN_ROW + ch * 16,
             src + ((size_t)b * CQ_ + r) * N_ + col + ch * 8);
    }
    CP_COMMIT();
    CP_WAIT(0);
    __syncthreads();

    float acc[2][8][4];
#pragma unroll
    for (int mt = 0; mt < 2; mt++)
#pragma unroll
        for (int t = 0; t < 8; t++)
#pragma unroll
            for (int q = 0; q < 4; q++) acc[mt][t][q] = 0.f;

    // A (trans from Q [q][i]): row = ks*16 + (lane&7) + ((lane>>4)<<3)
    //                          colb = (warp_m*32 + mt*16 + ((lane>>3)&1)*8) * 2
    const uint32_t aq_row = (uint32_t)((lane & 7) | ((lane >> 4) << 3));
    const uint32_t aq_col = (uint32_t)((warp_m * 32 + ((lane >> 3) & 1) * 8) * 2);
    // B (trans from K [q][j]): row = ks*16 + (lane&7)+(lane&8)
    //                          colb = (warp_n*64 + ng*16 + ((lane>>4)&1)*8) * 2
    const uint32_t bk_row = (uint32_t)((lane & 7) | (lane & 8));
    const uint32_t bk_col = (uint32_t)((warp_n * 64 + ((lane >> 4) & 1) * 8) * 2);

#pragma unroll
    for (int ks = 0; ks < 4; ks++) {
        uint32_t ah[2][4], al[2][4];
#pragma unroll
        for (int mt = 0; mt < 2; mt++) {
            uint32_t aoff = (aq_row + ks * 16) * EN_ROW + aq_col + mt * 32;
            ldm_x4t(ah[mt], base + EN_QH + aoff);
            ldm_x4t(al[mt], base + EN_QL + aoff);
        }
#pragma unroll
        for (int ng = 0; ng < 4; ng++) {
            uint32_t boff = (bk_row + ks * 16) * EN_ROW + bk_col + ng * 32;
            uint32_t bh[4], bl[4];
            ldm_x4t(bh, base + EN_KH + boff);
            ldm_x4t(bl, base + EN_KL + boff);
#pragma unroll
            for (int mt = 0; mt < 2; mt++)
#pragma unroll
                for (int sub = 0; sub < 2; sub++) {
                    float* a = acc[mt][ng * 2 + sub];
                    uint32_t p0 = sub ? bh[2] : bh[0], p1 = sub ? bh[3] : bh[1];
                    uint32_t q0 = sub ? bl[2] : bl[0], q1 = sub ? bl[3] : bl[1];
                    mma16816(a, ah[mt], p0, p1);
                    mma16816(a, ah[mt], q0, q1);
                    mma16816(a, al[mt], p0, p1);
                }
        }
    }

    // epilogue: exp, split-store, partial rowsums
    const int gp = lane >> 2, tg = lane & 3;
    float rs[2][2] = {{0.f, 0.f}, {0.f, 0.f}};
#pragma unroll
    for (int mt = 0; mt < 2; mt++) {
        const int r0 = i0 + warp_m * 32 + mt * 16 + gp;
#pragma unroll
        for (int t = 0; t < 8; t++) {
            const int jc = j0 + warp_n * 64 + t * 8 + tg * 2;
            float e0 = __expf(acc[mt][t][0] * SCALE_);
            float e1 = __expf(acc[mt][t][1] * SCALE_);
            float e2 = __expf(acc[mt][t][2] * SCALE_);
            float e3 = __expf(acc[mt][t][3] * SCALE_);
            rs[mt][0] += e0 + e1;
            rs[mt][1] += e2 + e3;
            size_t a0 = ((size_t)b * N_ + r0) * N_ + jc;
            size_t a1 = a0 + 8 * (size_t)N_;
            __nv_bfloat16 h0,l0,h1,l1;
            split_bf16(e0, h0, l0); split_bf16(e1, h1, l1);
            *(uint32_t*)(g_ph + a0) = pack2(h0, h1);
            *(uint32_t*)(g_pl + a0) = pack2(l0, l1);
            split_bf16(e2, h0, l0); split_bf16(e3, h1, l1);
            *(uint32_t*)(g_ph + a1) = pack2(h0, h1);
            *(uint32_t*)(g_pl + a1) = pack2(l0, l1);
        }
    }
#pragma unroll
    for (int mt = 0; mt < 2; mt++)
#pragma unroll
        for (int h = 0; h < 2; h++) {
            float s = rs[mt][h];
            s += __shfl_xor_sync(0xFFFFFFFF, s, 1);
            s += __shfl_xor_sync(0xFFFFFFFF, s, 2);
            if (tg == 0)
                ps[warp_n * 128 + warp_m * 32 + mt * 16 + h * 8 + gp] = s;
        }
    __syncthreads();
    if (tid < 128)
        g_psum[((size_t)b * 32 + jt) * N_ + i0 + tid] = ps[tid] + ps[128 + tid];
}

// ---------------------------------------------------------------------------
// rowsum reduce: inv[b][i] = 1 / sum_jt psum[b][jt][i]
// ---------------------------------------------------------------------------
__global__ __launch_bounds__(256) void rowsum_reduce_kernel()
{
    const int r = blockIdx.x * 256 + threadIdx.x;   // b*N_ + i
    const int b = r >> 12, i = r & (N_ - 1);
    float s = 0.f;
#pragma unroll
    for (int jt = 0; jt < 32; jt++)
        s += g_psum[((size_t)b * 32 + jt) * N_ + i];
    g_inv[r] = 1.f / s;
}

// ---------------------------------------------------------------------------
// Output GEMM: D[c][i] = sum_j V[c][j] P[i][j]; out = D*inv + xs + xt
// CTA 128c x 256i, KC=64, 2 stages. Warps 4c x 2i.
// ---------------------------------------------------------------------------
#define OUT_ROW 144
#define OUT_AH 0
#define OUT_AL (128 * OUT_ROW)            // 18432
#define OUT_BH (2 * 128 * OUT_ROW)        // 36864
#define OUT_BL (2 * 128 * OUT_ROW + 256 * OUT_ROW)  // 73728
#define OUT_STAGE (2 * 128 * OUT_ROW + 2 * 256 * OUT_ROW)  // 110592
#define OUT_INV (2 * OUT_STAGE)
#define OUT_SMEM (2 * OUT_STAGE + 1024 + 1024)

__device__ __forceinline__ void out_load_stage(uint32_t sb, int b, int c0, int i0, int j0, int tid)
{
#pragma unroll
    for (int k = 0; k < 8; k++) {          // A: 2 mats x 128 rows x 8 chunks
        int idx = tid + k * 256;
        int row = (idx >> 3) & 127, ch = idx & 7;
        int hl = idx >> 10;
        uint32_t soff = (hl ? OUT_AL : OUT_AH) + row * OUT_ROW + ch * 16;
        const __nv_bfloat16* src = hl ? g_vl : g_vh;
        cp16(sb + soff, src + ((size_t)(b * C_ + c0 + row)) * N_ + j0 + ch * 8);
    }
#pragma unroll
    for (int k = 0; k < 16; k++) {         // B: 2 mats x 256 rows x 8 chunks
        int idx = tid + k * 256;
        int row = (idx >> 3) & 255, ch = idx & 7;
        int hl = idx >> 11;
        uint32_t soff = (hl ? OUT_BL : OUT_BH) + row * OUT_ROW + ch * 16;
        const __nv_bfloat16* src = hl ? g_pl : g_ph;
        cp16(sb + soff, src + ((size_t)b * N_ + i0 + row) * N_ + j0 + ch * 8);
    }
    CP_COMMIT();
}

__global__ __launch_bounds__(256, 1) void out_mma_kernel(
    const float* __restrict__ xs, const float* __restrict__ xt,
    float* __restrict__ out)
{
    extern __shared__ char dsm[];
    uint32_t raw  = smem_u32(dsm);
    uint32_t base = (raw + 1023) & ~1023u;
    float* inv_s  = (float*)(dsm + (base - raw) + OUT_INV);

    const int tid = threadIdx.x;
    const int lane = tid & 31;
    const int wid = tid >> 5;
    const int warp_m = wid & 3;      // c: 32 rows
    const int warp_n = wid >> 2;     // i: 128 cols

    const int b  = blockIdx.z;
    const int c0 = blockIdx.x * 128;
    const int i0 = blockIdx.y * 256;

    float acc[2][16][4];
#pragma unroll
    for (int mt = 0; mt < 2; mt++)
#pragma unroll
        for (int t = 0; t < 16; t++)
#pragma unroll
            for (int q = 0; q < 4; q++) acc[mt][t][q] = 0.f;

    out_load_stage(base,             b, c0, i0, 0,  tid);
    out_load_stage(base + OUT_STAGE, b, c0, i0, 64, tid);

    const int lrow = lane & 15;
    const int lkh  = (lane >> 4) * 16;

    for (int chk = 0; chk < 64; chk++) {
        const uint32_t sb = base + (chk & 1) * OUT_STAGE;
        if (chk == 63) CP_WAIT(0); else CP_WAIT(1);
        __syncthreads();

        const uint32_t a_base = sb + (warp_m * 32 + lrow) * OUT_ROW + lkh;
        const uint32_t b_base = sb + (warp_n * 128 + lrow) * OUT_ROW + lkh;

#pragma unroll
        for (int ks = 0; ks < 4; ks++) {
            const uint32_t koff = ks * 32;
            uint32_t ah[2][4], al[2][4];
#pragma unroll
            for (int mt = 0; mt < 2; mt++) {
                ldm_x4(ah[mt], a_base + OUT_AH + mt * (16 * OUT_ROW) + koff);
                ldm_x4(al[mt], a_base + OUT_AL + mt * (16 * OUT_ROW) + koff);
            }
#pragma unroll
            for (int ng = 0; ng < 8; ng++) {
                uint32_t bh[4], bl[4];
                ldm_x4(bh, b_base + OUT_BH + ng * (16 * OUT_ROW) + koff);
                ldm_x4(bl, b_base + OUT_BL + ng * (16 * OUT_ROW) + koff);
#pragma unroll
                for (int mt = 0; mt < 2; mt++) {
                    mma16816(acc[mt][ng*2],   ah[mt], bh[0], bh[2]);
                    mma16816(acc[mt][ng*2],   ah[mt], bl[0], bl[2]);
                    mma16816(acc[mt][ng*2],   al[mt], bh[0], bh[2]);
                    mma16816(acc[mt][ng*2+1], ah[mt], bh[1], bh[3]);
                    mma16816(acc[mt][ng*2+1], ah[mt], bl[1], bl[3]);
                    mma16816(acc[mt][ng*2+1], al[mt], bh[1], bh[3]);
                }
            }
        }
        __syncthreads();
        if (chk + 2 < 64) out_load_stage(sb, b, c0, i0, (chk + 2) * 64, tid);
    }

    inv_s[tid] = g_inv[b * N_ + i0 + tid];
    __syncthreads();

    const int gp = lane >> 2, tg = lane & 3;
#pragma unroll
    for (int mt = 0; mt < 2; mt++) {
        const int c = c0 + warp_m * 32 + mt * 16 + gp;
#pragma unroll
        for (int t = 0; t < 16; t++) {
            const int iloc = warp_n * 128 + t * 8 + tg * 2;
            const float inv0 = inv_s[iloc], inv1 = inv_s[iloc + 1];
            size_t g0 = ((size_t)(b * C_ + c)) * N_ + i0 + iloc;
            size_t g1 = g0 + 8 * (size_t)N_;
            float2 x1 = *(const float2*)(xs + g0);
            float2 x2 = *(const float2*)(xt + g0);
            float2 r0;
            r0.x = acc[mt][t][0] * inv0 + x1.x + x2.x;
            r0.y = acc[mt][t][1] * inv1 + x1.y + x2.y;
            *(float2*)(out + g0) = r0;
            float2 x3 = *(const float2*)(xs + g1);
            float2 x4 = *(const float2*)(xt + g1);
            float2 r1;
            r1.x = acc[mt][t][2] * inv0 + x3.x + x4.x;
            r1.y = acc[mt][t][3] * inv1 + x3.y + x4.y;
            *(float2*)(out + g1) = r1;
        }
    }
}

// ---------------------------------------------------------------------------
extern "C" void kernel_launch(void* const* d_in, const int* in_sizes, int n_in,
                              void* d_out, int out_size)
{
    const float* xs  = (const float*)d_in[0];
    const float* xt  = (const float*)d_in[1];
    const float* Wq  = (const float*)d_in[2];
    const float* bq  = (const float*)d_in[3];
    const float* Wk  = (const float*)d_in[4];
    const float* bk  = (const float*)d_in[5];
    const float* Wvs = (const float*)d_in[6];
    const float* bvs = (const float*)d_in[7];
    const float* Wvt = (const float*)d_in[8];
    const float* bvt = (const float*)d_in[9];
    float* out = (float*)d_out;

    static bool attr_done = false;
    if (!attr_done) {
        cudaFuncSetAttribute(v_proj_mma_kernel, cudaFuncAttributeMaxDynamicSharedMemorySize, VP_SMEM);
        cudaFuncSetAttribute(energy_exp_kernel, cudaFuncAttributeMaxDynamicSharedMemorySize, EN_SMEM);
        cudaFuncSetAttribute(out_mma_kernel,   cudaFuncAttributeMaxDynamicSharedMemorySize, OUT_SMEM);
        attr_done = true;
    }

    w_split_kernel<<<dim3(C_ * C_ / 1024, 2), 256>>>(Wvs, Wvt);
    x_split_kernel<<<dim3(B_ * C_ * N_ / 1024, 2), 256>>>(xs, xt);
    qk_proj_kernel<<<dim3(N_ / 128, B_), 256>>>(Wq, bq, xs, 0);
    qk_proj_kernel<<<dim3(N_ / 128, B_), 256>>>(Wk, bk, xt, 1);
    v_proj_mma_kernel<<<dim3(N_ / 128, C_ / 128, B_), 256, VP_SMEM>>>(bvs, bvt);
    energy_exp_kernel<<<dim3(N_ / 128, N_ / 128, B_), 256, EN_SMEM>>>();
    rowsum_reduce_kernel<<<B_ * N_ / 256, 256>>>();
    out_mma_kernel<<<dim3(C_ / 128, N_ / 256, B_), 256, OUT_SMEM>>>(xs, xt, out);
}

// round 5
// speedup vs baseline: 6.1896x; 2.2356x over previous
#include <cuda_runtime.h>
#include <cuda_bf16.h>
#include <cstdint>
#include <cstddef>

#define B_   4
#define C_   512
#define N_   4096
#define CQ_  64
#define SCALE_ 0.125f   // (C/8)^-0.5

// ---------------- device scratch (single bf16) ----------
__device__ __nv_bfloat16 g_q[B_ * CQ_ * N_];                  // [b][q][n]
__device__ __nv_bfloat16 g_k[B_ * CQ_ * N_];
__device__ __nv_bfloat16 g_v[(size_t)B_ * C_ * N_];           // [b][c][n]
__device__ __nv_bfloat16 g_p[(size_t)B_ * N_ * N_];           // exp(E) [b][i][j]
__device__ __nv_bfloat16 g_xs[(size_t)B_ * C_ * N_];          // x bf16
__device__ __nv_bfloat16 g_xt[(size_t)B_ * C_ * N_];
__device__ __nv_bfloat16 g_ws[C_ * C_], g_wt[C_ * C_];        // Wvs/Wvt bf16 [c][k]
__device__ float g_psum[B_ * 32 * N_];                        // [b][jt][i]
__device__ float g_inv[B_ * N_];

#define LD8(dst, ptr)                                              \
    do {                                                           \
        float4 _u0 = *(const float4*)((ptr));                      \
        float4 _u1 = *(const float4*)((ptr) + 4);                  \
        (dst)[0]=_u0.x; (dst)[1]=_u0.y; (dst)[2]=_u0.z; (dst)[3]=_u0.w; \
        (dst)[4]=_u1.x; (dst)[5]=_u1.y; (dst)[6]=_u1.z; (dst)[7]=_u1.w; \
    } while (0)

// ====================== helpers ======================
__device__ __forceinline__ uint32_t smem_u32(const void* p) {
    uint32_t a;
    asm("{ .reg .u64 t; cvta.to.shared.u64 t, %1; cvt.u32.u64 %0, t; }" : "=r"(a) : "l"(p));
    return a;
}
__device__ __forceinline__ void cp16(uint32_t dst, const void* src) {
    asm volatile("cp.async.cg.shared.global [%0], [%1], 16;" :: "r"(dst), "l"(src));
}
#define CP_COMMIT() asm volatile("cp.async.commit_group;" ::: "memory")
#define CP_WAIT(n)  asm volatile("cp.async.wait_group %0;" :: "n"(n) : "memory")
__device__ __forceinline__ void ldm_x4(uint32_t* r, uint32_t addr) {
    asm volatile("ldmatrix.sync.aligned.m8n8.x4.shared.b16 {%0,%1,%2,%3}, [%4];"
        : "=r"(r[0]), "=r"(r[1]), "=r"(r[2]), "=r"(r[3]) : "r"(addr));
}
__device__ __forceinline__ void ldm_x4t(uint32_t* r, uint32_t addr) {
    asm volatile("ldmatrix.sync.aligned.m8n8.x4.trans.shared.b16 {%0,%1,%2,%3}, [%4];"
        : "=r"(r[0]), "=r"(r[1]), "=r"(r[2]), "=r"(r[3]) : "r"(addr));
}
__device__ __forceinline__ void mma16816(float* c, const uint32_t* a, uint32_t b0, uint32_t b1) {
    asm volatile(
        "mma.sync.aligned.m16n8k16.row.col.f32.bf16.bf16.f32 "
        "{%0,%1,%2,%3}, {%4,%5,%6,%7}, {%8,%9}, {%0,%1,%2,%3};"
        : "+f"(c[0]), "+f"(c[1]), "+f"(c[2]), "+f"(c[3])
        : "r"(a[0]), "r"(a[1]), "r"(a[2]), "r"(a[3]), "r"(b0), "r"(b1));
}
__device__ __forceinline__ uint32_t pack2f(float a, float b) {
    __nv_bfloat162 t; t.x = __float2bfloat16(a); t.y = __float2bfloat16(b);
    return *(uint32_t*)&t;
}

// ---------------------------------------------------------------------------
// Converts: fp32 -> bf16
// ---------------------------------------------------------------------------
__global__ __launch_bounds__(256) void x_cvt_kernel(
    const float* __restrict__ xs, const float* __restrict__ xt)
{
    const size_t idx4 = ((size_t)blockIdx.x * 256 + threadIdx.x) * 4;
    const float* src = blockIdx.y ? xt : xs;
    __nv_bfloat16* dst = blockIdx.y ? g_xt : g_xs;
    float4 v = *(const float4*)(src + idx4);
    uint32_t* p = (uint32_t*)(dst + idx4);
    p[0] = pack2f(v.x, v.y);
    p[1] = pack2f(v.z, v.w);
}

__global__ __launch_bounds__(256) void w_cvt_kernel(
    const float* __restrict__ Wvs, const float* __restrict__ Wvt)
{
    const size_t idx4 = ((size_t)blockIdx.x * 256 + threadIdx.x) * 4;
    const float* src = blockIdx.y ? Wvt : Wvs;
    __nv_bfloat16* dst = blockIdx.y ? g_wt : g_ws;
    float4 v = *(const float4*)(src + idx4);
    uint32_t* p = (uint32_t*)(dst + idx4);
    p[0] = pack2f(v.x, v.y);
    p[1] = pack2f(v.z, v.w);
}

// ---------------------------------------------------------------------------
// Q/K projection fp32 -> bf16 out. blockIdx.z: 0 = Q (from xs), 1 = K (from xt)
// ---------------------------------------------------------------------------
__global__ __launch_bounds__(256) void qk_proj_kernel(
    const float* __restrict__ Wq, const float* __restrict__ bq,
    const float* __restrict__ Wk, const float* __restrict__ bk,
    const float* __restrict__ xs, const float* __restrict__ xt)
{
    __shared__ float Ws[32][68];
    __shared__ float Xs[32][128];

    const int which = blockIdx.z;
    const int b  = blockIdx.y;
    const int n0 = blockIdx.x * 128;
    const float* W = which ? Wk : Wq;
    const float* bias = which ? bk : bq;
    const float* Xb = (which ? xt : xs) + (size_t)b * C_ * N_;
    __nv_bfloat16* Y = which ? g_k : g_q;

    const int tid = threadIdx.x;
    const int tx = tid & 15;
    const int ty = tid >> 4;

    float acc[4][8];
#pragma unroll
    for (int i = 0; i < 4; i++)
#pragma unroll
        for (int j = 0; j < 8; j++) acc[i][j] = 0.f;

    for (int k0 = 0; k0 < C_; k0 += 32) {
#pragma unroll
        for (int r = 0; r < 8; r++) {
            int idx = tid + r * 256;
            int m = idx >> 5, kk = idx & 31;
            Ws[kk][m] = W[(size_t)m * C_ + k0 + kk];
        }
#pragma unroll
        for (int r = 0; r < 16; r++) {
            int idx = tid + r * 256;
            int kk = idx >> 7, n = idx & 127;
            Xs[kk][n] = Xb[(size_t)(k0 + kk) * N_ + n0 + n];
        }
        __syncthreads();
#pragma unroll
        for (int kk = 0; kk < 32; kk++) {
            float a[4], bb[8];
#pragma unroll
            for (int i = 0; i < 4; i++) a[i] = Ws[kk][ty * 4 + i];
            LD8(bb, &Xs[kk][tx * 8]);
#pragma unroll
            for (int i = 0; i < 4; i++)
#pragma unroll
                for (int j = 0; j < 8; j++) acc[i][j] += a[i] * bb[j];
        }
        __syncthreads();
    }
#pragma unroll
    for (int i = 0; i < 4; i++) {
        int m = ty * 4 + i;
        float bv = bias[m];
        uint32_t* yp = (uint32_t*)(Y + ((size_t)b * CQ_ + m) * N_ + n0 + tx * 8);
#pragma unroll
        for (int p = 0; p < 4; p++)
            yp[p] = pack2f(acc[i][2*p] + bv, acc[i][2*p+1] + bv);
    }
}

// ---------------------------------------------------------------------------
// V projection on mma.sync: V = Wvs@xs + Wvt@xt + bias  -> bf16
// CTA 128c x 128n, KC=32, 2 stages. Warps 4c x 2n.
// ---------------------------------------------------------------------------
#define VP_AROW 80                    // 64B + 16 pad
#define VP_BROW 272                   // 256B + 16 pad
#define VP_AMAT (128 * VP_AROW)       // 10240
#define VP_BMAT (32 * VP_BROW)        // 8704
#define VP_WS 0
#define VP_WT VP_AMAT
#define VP_XS (2 * VP_AMAT)
#define VP_XT (2 * VP_AMAT + VP_BMAT)
#define VP_STAGE (2 * VP_AMAT + 2 * VP_BMAT)   // 37888
#define VP_SMEM (2 * VP_STAGE + 1024)

__device__ __forceinline__ void vp_load_stage(uint32_t sb, int b, int c0, int n0, int k0, int tid)
{
#pragma unroll
    for (int k = 0; k < 4; k++) {          // A: 2 mats x 128 rows x 4 chunks
        int idx = tid + k * 256;
        int mat = idx >> 9, rem = idx & 511;
        int r = rem >> 2, ch = rem & 3;
        const __nv_bfloat16* src = mat ? g_wt : g_ws;
        cp16(sb + mat * VP_AMAT + r * VP_AROW + ch * 16,
             src + (size_t)(c0 + r) * C_ + k0 + ch * 8);
    }
#pragma unroll
    for (int k = 0; k < 4; k++) {          // B: 2 mats x 32 rows x 16 chunks
        int idx = tid + k * 256;
        int mat = idx >> 9, rem = idx & 511;
        int r = rem >> 4, ch = rem & 15;
        const __nv_bfloat16* src = mat ? g_xt : g_xs;
        cp16(sb + 2 * VP_AMAT + mat * VP_BMAT + r * VP_BROW + ch * 16,
             src + ((size_t)b * C_ + k0 + r) * N_ + n0 + ch * 8);
    }
    CP_COMMIT();
}

__global__ __launch_bounds__(256, 1) void v_proj_mma_kernel(
    const float* __restrict__ bvs, const float* __restrict__ bvt)
{
    extern __shared__ char dsm[];
    uint32_t raw  = smem_u32(dsm);
    uint32_t base = (raw + 1023) & ~1023u;

    const int tid = threadIdx.x;
    const int lane = tid & 31;
    const int wid = tid >> 5;
    const int warp_m = wid & 3;      // c: 32 rows
    const int warp_n = wid >> 2;     // n: 64 cols

    const int b  = blockIdx.z;
    const int c0 = blockIdx.y * 128;
    const int n0 = blockIdx.x * 128;

    float acc[2][8][4];
#pragma unroll
    for (int mt = 0; mt < 2; mt++)
#pragma unroll
        for (int t = 0; t < 8; t++)
#pragma unroll
            for (int q = 0; q < 4; q++) acc[mt][t][q] = 0.f;

    vp_load_stage(base,            b, c0, n0, 0,  tid);
    vp_load_stage(base + VP_STAGE, b, c0, n0, 32, tid);

    const uint32_t a_lrow = (uint32_t)(warp_m * 32 + (lane & 15));
    const uint32_t a_lcol = (uint32_t)((lane >> 4) * 16);
    const uint32_t b_lrow = (uint32_t)((lane & 7) | (lane & 8));
    const uint32_t b_lcol = (uint32_t)((warp_n * 64 + ((lane >> 4) & 1) * 8) * 2);

    for (int chk = 0; chk < 16; chk++) {
        const uint32_t sb = base + (chk & 1) * VP_STAGE;
        if (chk == 15) CP_WAIT(0); else CP_WAIT(1);
        __syncthreads();

#pragma unroll
        for (int ks = 0; ks < 2; ks++) {
            uint32_t ws[2][4], wt[2][4];
#pragma unroll
            for (int mt = 0; mt < 2; mt++) {
                uint32_t aoff = (a_lrow + mt * 16) * VP_AROW + a_lcol + ks * 32;
                ldm_x4(ws[mt], sb + VP_WS + aoff);
                ldm_x4(wt[mt], sb + VP_WT + aoff);
            }
#pragma unroll
            for (int ng = 0; ng < 4; ng++) {
                uint32_t boff = (b_lrow + ks * 16) * VP_BROW + b_lcol + ng * 32;
                uint32_t xsf[4], xtf[4];
                ldm_x4t(xsf, sb + VP_XS + boff);
                ldm_x4t(xtf, sb + VP_XT + boff);
#pragma unroll
                for (int mt = 0; mt < 2; mt++)
#pragma unroll
                    for (int sub = 0; sub < 2; sub++) {
                        float* a = acc[mt][ng * 2 + sub];
                        uint32_t s0 = sub ? xsf[2] : xsf[0], s1 = sub ? xsf[3] : xsf[1];
                        uint32_t t0 = sub ? xtf[2] : xtf[0], t1 = sub ? xtf[3] : xtf[1];
                        mma16816(a, ws[mt], s0, s1);
                        mma16816(a, wt[mt], t0, t1);
                    }
            }
        }
        __syncthreads();
        if (chk + 2 < 16) vp_load_stage(sb, b, c0, n0, (chk + 2) * 32, tid);
    }

    const int gp = lane >> 2, tg = lane & 3;
#pragma unroll
    for (int mt = 0; mt < 2; mt++) {
        const int r0 = c0 + warp_m * 32 + mt * 16 + gp;
        const float bv0 = bvs[r0] + bvt[r0];
        const float bv1 = bvs[r0 + 8] + bvt[r0 + 8];
#pragma unroll
        for (int t = 0; t < 8; t++) {
            const int nc = n0 + warp_n * 64 + t * 8 + tg * 2;
            size_t i0 = ((size_t)b * C_ + r0) * N_ + nc;
            size_t i1 = i0 + 8 * (size_t)N_;
            *(uint32_t*)(g_v + i0) = pack2f(acc[mt][t][0] + bv0, acc[mt][t][1] + bv0);
            *(uint32_t*)(g_v + i1) = pack2f(acc[mt][t][2] + bv1, acc[mt][t][3] + bv1);
        }
    }
}

// ---------------------------------------------------------------------------
// Energy + exp (fused): P = exp(SCALE * Q^T K) -> bf16 + partial rowsums
// CTA 128i x 128j; K = CQ = 64. Warps 4i x 2j.
// ---------------------------------------------------------------------------
#define EN_ROW 272                    // 256B + 16
#define EN_MAT (64 * EN_ROW)          // 17408
#define EN_Q 0
#define EN_K EN_MAT
#define EN_PS (2 * EN_MAT)            // 2 x 128 floats
#define EN_SMEM (2 * EN_MAT + 1024 + 1024)

__global__ __launch_bounds__(256, 1) void energy_exp_kernel()
{
    extern __shared__ char dsm[];
    uint32_t raw  = smem_u32(dsm);
    uint32_t base = (raw + 1023) & ~1023u;
    float* ps = (float*)(dsm + (base - raw) + EN_PS);

    const int tid = threadIdx.x;
    const int lane = tid & 31;
    const int wid = tid >> 5;
    const int warp_m = wid & 3;      // i
    const int warp_n = wid >> 2;     // j

    const int b  = blockIdx.z;
    const int i0 = blockIdx.y * 128;
    const int jt = blockIdx.x;
    const int j0 = jt * 128;

    // load Q,K tiles: 2 mats x 64 rows x 16 chunks
#pragma unroll
    for (int k = 0; k < 8; k++) {
        int idx = tid + k * 256;
        int mat = idx >> 10, rem = idx & 1023;
        int r = rem >> 4, ch = rem & 15;
        const __nv_bfloat16* src = mat ? g_k : g_q;
        int col = mat ? j0 : i0;
        cp16(base + mat * EN_MAT + r * EN_ROW + ch * 16,
             src + ((size_t)b * CQ_ + r) * N_ + col + ch * 8);
    }
    CP_COMMIT();
    CP_WAIT(0);
    __syncthreads();

    float acc[2][8][4];
#pragma unroll
    for (int mt = 0; mt < 2; mt++)
#pragma unroll
        for (int t = 0; t < 8; t++)
#pragma unroll
            for (int q = 0; q < 4; q++) acc[mt][t][q] = 0.f;

    const uint32_t aq_row = (uint32_t)((lane & 7) | ((lane >> 4) << 3));
    const uint32_t aq_col = (uint32_t)((warp_m * 32 + ((lane >> 3) & 1) * 8) * 2);
    const uint32_t bk_row = (uint32_t)((lane & 7) | (lane & 8));
    const uint32_t bk_col = (uint32_t)((warp_n * 64 + ((lane >> 4) & 1) * 8) * 2);

#pragma unroll
    for (int ks = 0; ks < 4; ks++) {
        uint32_t ah[2][4];
#pragma unroll
        for (int mt = 0; mt < 2; mt++) {
            uint32_t aoff = (aq_row + ks * 16) * EN_ROW + aq_col + mt * 32;
            ldm_x4t(ah[mt], base + EN_Q + aoff);
        }
#pragma unroll
        for (int ng = 0; ng < 4; ng++) {
            uint32_t boff = (bk_row + ks * 16) * EN_ROW + bk_col + ng * 32;
            uint32_t bh[4];
            ldm_x4t(bh, base + EN_K + boff);
#pragma unroll
            for (int mt = 0; mt < 2; mt++)
#pragma unroll
                for (int sub = 0; sub < 2; sub++) {
                    float* a = acc[mt][ng * 2 + sub];
                    uint32_t p0 = sub ? bh[2] : bh[0], p1 = sub ? bh[3] : bh[1];
                    mma16816(a, ah[mt], p0, p1);
                }
        }
    }

    // epilogue: exp, bf16 store, partial rowsums
    const int gp = lane >> 2, tg = lane & 3;
    float rs[2][2] = {{0.f, 0.f}, {0.f, 0.f}};
#pragma unroll
    for (int mt = 0; mt < 2; mt++) {
        const int r0 = i0 + warp_m * 32 + mt * 16 + gp;
#pragma unroll
        for (int t = 0; t < 8; t++) {
            const int jc = j0 + warp_n * 64 + t * 8 + tg * 2;
            float e0 = __expf(acc[mt][t][0] * SCALE_);
            float e1 = __expf(acc[mt][t][1] * SCALE_);
            float e2 = __expf(acc[mt][t][2] * SCALE_);
            float e3 = __expf(acc[mt][t][3] * SCALE_);
            rs[mt][0] += e0 + e1;
            rs[mt][1] += e2 + e3;
            size_t a0 = ((size_t)b * N_ + r0) * N_ + jc;
            size_t a1 = a0 + 8 * (size_t)N_;
            *(uint32_t*)(g_p + a0) = pack2f(e0, e1);
            *(uint32_t*)(g_p + a1) = pack2f(e2, e3);
        }
    }
#pragma unroll
    for (int mt = 0; mt < 2; mt++)
#pragma unroll
        for (int h = 0; h < 2; h++) {
            float s = rs[mt][h];
            s += __shfl_xor_sync(0xFFFFFFFF, s, 1);
            s += __shfl_xor_sync(0xFFFFFFFF, s, 2);
            if (tg == 0)
                ps[warp_n * 128 + warp_m * 32 + mt * 16 + h * 8 + gp] = s;
        }
    __syncthreads();
    if (tid < 128)
        g_psum[((size_t)b * 32 + jt) * N_ + i0 + tid] = ps[tid] + ps[128 + tid];
}

// ---------------------------------------------------------------------------
__global__ __launch_bounds__(256) void rowsum_reduce_kernel()
{
    const int r = blockIdx.x * 256 + threadIdx.x;
    const int b = r >> 12, i = r & (N_ - 1);
    float s = 0.f;
#pragma unroll
    for (int jt = 0; jt < 32; jt++)
        s += g_psum[((size_t)b * 32 + jt) * N_ + i];
    g_inv[r] = 1.f / s;
}

// ---------------------------------------------------------------------------
// Output GEMM: D[c][i] = sum_j V[c][j] P[i][j]; out = D*inv + xs + xt
// CTA 128c x 256i, KC=64, 2 stages. Warps 4c x 2i.
// ---------------------------------------------------------------------------
#define OUT_ROW 144
#define OUT_A 0
#define OUT_B (128 * OUT_ROW)                 // 18432
#define OUT_STAGE (128 * OUT_ROW + 256 * OUT_ROW)  // 55296
#define OUT_INV (2 * OUT_STAGE)
#define OUT_SMEM (2 * OUT_STAGE + 1024 + 1024)

__device__ __forceinline__ void out_load_stage(uint32_t sb, int b, int c0, int i0, int j0, int tid)
{
#pragma unroll
    for (int k = 0; k < 4; k++) {          // A: 128 rows x 8 chunks
        int idx = tid + k * 256;
        int row = idx >> 3, ch = idx & 7;
        cp16(sb + OUT_A + row * OUT_ROW + ch * 16,
             g_v + ((size_t)(b * C_ + c0 + row)) * N_ + j0 + ch * 8);
    }
#pragma unroll
    for (int k = 0; k < 8; k++) {          // B: 256 rows x 8 chunks
        int idx = tid + k * 256;
        int row = idx >> 3, ch = idx & 7;
        cp16(sb + OUT_B + row * OUT_ROW + ch * 16,
             g_p + ((size_t)b * N_ + i0 + row) * N_ + j0 + ch * 8);
    }
    CP_COMMIT();
}

__global__ __launch_bounds__(256, 1) void out_mma_kernel(
    const float* __restrict__ xs, const float* __restrict__ xt,
    float* __restrict__ out)
{
    extern __shared__ char dsm[];
    uint32_t raw  = smem_u32(dsm);
    uint32_t base = (raw + 1023) & ~1023u;
    float* inv_s  = (float*)(dsm + (base - raw) + OUT_INV);

    const int tid = threadIdx.x;
    const int lane = tid & 31;
    const int wid = tid >> 5;
    const int warp_m = wid & 3;      // c: 32 rows
    const int warp_n = wid >> 2;     // i: 128 cols

    const int b  = blockIdx.z;
    const int c0 = blockIdx.x * 128;
    const int i0 = blockIdx.y * 256;

    float acc[2][16][4];
#pragma unroll
    for (int mt = 0; mt < 2; mt++)
#pragma unroll
        for (int t = 0; t < 16; t++)
#pragma unroll
            for (int q = 0; q < 4; q++) acc[mt][t][q] = 0.f;

    out_load_stage(base,             b, c0, i0, 0,  tid);
    out_load_stage(base + OUT_STAGE, b, c0, i0, 64, tid);

    const int lrow = lane & 15;
    const int lkh  = (lane >> 4) * 16;

    for (int chk = 0; chk < 64; chk++) {
        const uint32_t sb = base + (chk & 1) * OUT_STAGE;
        if (chk == 63) CP_WAIT(0); else CP_WAIT(1);
        __syncthreads();

        const uint32_t a_base = sb + OUT_A + (warp_m * 32 + lrow) * OUT_ROW + lkh;
        const uint32_t b_base = sb + OUT_B + (warp_n * 128 + lrow) * OUT_ROW + lkh;

#pragma unroll
        for (int ks = 0; ks < 4; ks++) {
            const uint32_t koff = ks * 32;
            uint32_t ah[2][4];
#pragma unroll
            for (int mt = 0; mt < 2; mt++)
                ldm_x4(ah[mt], a_base + mt * (16 * OUT_ROW) + koff);
#pragma unroll
            for (int ng = 0; ng < 8; ng++) {
                uint32_t bh[4];
                ldm_x4(bh, b_base + ng * (16 * OUT_ROW) + koff);
#pragma unroll
                for (int mt = 0; mt < 2; mt++) {
                    mma16816(acc[mt][ng*2],   ah[mt], bh[0], bh[2]);
                    mma16816(acc[mt][ng*2+1], ah[mt], bh[1], bh[3]);
                }
            }
        }
        __syncthreads();
        if (chk + 2 < 64) out_load_stage(sb, b, c0, i0, (chk + 2) * 64, tid);
    }

    inv_s[tid] = g_inv[b * N_ + i0 + tid];
    __syncthreads();

    const int gp = lane >> 2, tg = lane & 3;
#pragma unroll
    for (int mt = 0; mt < 2; mt++) {
        const int c = c0 + warp_m * 32 + mt * 16 + gp;
#pragma unroll
        for (int t = 0; t < 16; t++) {
            const int iloc = warp_n * 128 + t * 8 + tg * 2;
            const float inv0 = inv_s[iloc], inv1 = inv_s[iloc + 1];
            size_t g0 = ((size_t)(b * C_ + c)) * N_ + i0 + iloc;
            size_t g1 = g0 + 8 * (size_t)N_;
            float2 x1 = *(const float2*)(xs + g0);
            float2 x2 = *(const float2*)(xt + g0);
            float2 r0;
            r0.x = acc[mt][t][0] * inv0 + x1.x + x2.x;
            r0.y = acc[mt][t][1] * inv1 + x1.y + x2.y;
            *(float2*)(out + g0) = r0;
            float2 x3 = *(const float2*)(xs + g1);
            float2 x4 = *(const float2*)(xt + g1);
            float2 r1;
            r1.x = acc[mt][t][2] * inv0 + x3.x + x4.x;
            r1.y = acc[mt][t][3] * inv1 + x3.y + x4.y;
            *(float2*)(out + g1) = r1;
        }
    }
}

// ---------------------------------------------------------------------------
extern "C" void kernel_launch(void* const* d_in, const int* in_sizes, int n_in,
                              void* d_out, int out_size)
{
    const float* xs  = (const float*)d_in[0];
    const float* xt  = (const float*)d_in[1];
    const float* Wq  = (const float*)d_in[2];
    const float* bq  = (const float*)d_in[3];
    const float* Wk  = (const float*)d_in[4];
    const float* bk  = (const float*)d_in[5];
    const float* Wvs = (const float*)d_in[6];
    const float* bvs = (const float*)d_in[7];
    const float* Wvt = (const float*)d_in[8];
    const float* bvt = (const float*)d_in[9];
    float* out = (float*)d_out;

    static bool attr_done = false;
    if (!attr_done) {
        cudaFuncSetAttribute(v_proj_mma_kernel, cudaFuncAttributeMaxDynamicSharedMemorySize, VP_SMEM);
        cudaFuncSetAttribute(energy_exp_kernel, cudaFuncAttributeMaxDynamicSharedMemorySize, EN_SMEM);
        cudaFuncSetAttribute(out_mma_kernel,   cudaFuncAttributeMaxDynamicSharedMemorySize, OUT_SMEM);
        attr_done = true;
    }

    w_cvt_kernel<<<dim3(C_ * C_ / 1024, 2), 256>>>(Wvs, Wvt);
    x_cvt_kernel<<<dim3(B_ * C_ * N_ / 1024, 2), 256>>>(xs, xt);
    qk_proj_kernel<<<dim3(N_ / 128, B_, 2), 256>>>(Wq, bq, Wk, bk, xs, xt);
    v_proj_mma_kernel<<<dim3(N_ / 128, C_ / 128, B_), 256, VP_SMEM>>>(bvs, bvt);
    energy_exp_kernel<<<dim3(N_ / 128, N_ / 128, B_), 256, EN_SMEM>>>();
    rowsum_reduce_kernel<<<B_ * N_ / 256, 256>>>();
    out_mma_kernel<<<dim3(C_ / 128, N_ / 256, B_), 256, OUT_SMEM>>>(xs, xt, out);
}